// round 16
// baseline (speedup 1.0000x reference)
#include <cuda_runtime.h>
#include <math.h>

// X is (65536, 512) fp32 row-major.
// Base: record config (R6, 78.1us; reconfirmed R15 at 78.9us).
// SINGLE CHANGE vs record: pass3 batches 2 row-pair loads before any
// compute/store (same lever that took pass1 31->25.9us in R6). Everything
// else byte-identical.
#define CDIM 512
#define BDIM 65536
#define NB1  2048            // pass-1 blocks: 32 rows each -> 1 partial row
#define R1   (BDIM / NB1)    // 32 rows per block, 16 per parity
#define NB2  64              // stage-2a blocks: each reduces 32 partial rows
#define NB3  2048            // pass-3 blocks (32 rows each)
#define R3   (BDIM / NB3)    // 32

// Static device scratch (no allocations allowed).
__device__ __align__(16) float g_sumP[NB1][CDIM];
__device__ __align__(16) float g_maxP[NB1][CDIM];
__device__ __align__(16) float g_minP[NB1][CDIM];
__device__ __align__(16) float g_sum2[NB2][CDIM];
__device__ __align__(16) float g_max2[NB2][CDIM];
__device__ __align__(16) float g_min2[NB2][CDIM];
__device__ __align__(16) float g_mean[CDIM];
__device__ __align__(16) float g_c1[CDIM];
__device__ __align__(16) float g_c2[CDIM];
__device__ __align__(16) float g_wc[CDIM];
__device__ float g_sn1;

// ---------------------------------------------------------------------------
// Pass 1: per-column partial sum/max/min. Block b covers rows [b*32,(b+1)*32);
// 256 threads = 128 float4 column-groups x 2 row parities (16 rows each).
// Loads issued in explicit batches of 4 before accumulation (MLP >= 4).
// Default cache policy on X (pass3 harvests the L2-resident tail);
// partial writes __stcs so they don't evict X.
// ---------------------------------------------------------------------------
__global__ void __launch_bounds__(256) k_pass1(const float* __restrict__ X) {
    const int tc = threadIdx.x & 127;   // column group 0..127
    const int tr = threadIdx.x >> 7;    // row parity 0..1
    const int b = blockIdx.x;
    const float4* Xp = reinterpret_cast<const float4*>(X);
    size_t base = ((size_t)b * R1 + tr) * (CDIM / 4) + tc;
    const size_t rs = CDIM / 4;         // float4 row stride

    float4 s  = make_float4(0.f, 0.f, 0.f, 0.f);
    float4 mx = make_float4(-INFINITY, -INFINITY, -INFINITY, -INFINITY);
    float4 mn = make_float4( INFINITY,  INFINITY,  INFINITY,  INFINITY);

#pragma unroll
    for (int rr = 0; rr < R1 / 2; rr += 4) {        // 16 rows per parity
        float4 v0 = Xp[base + (size_t)(2 * rr + 0) * rs];
        float4 v1 = Xp[base + (size_t)(2 * rr + 2) * rs];
        float4 v2 = Xp[base + (size_t)(2 * rr + 4) * rs];
        float4 v3 = Xp[base + (size_t)(2 * rr + 6) * rs];

        s.x += v0.x; s.y += v0.y; s.z += v0.z; s.w += v0.w;
        mx.x = fmaxf(mx.x, v0.x); mx.y = fmaxf(mx.y, v0.y);
        mx.z = fmaxf(mx.z, v0.z); mx.w = fmaxf(mx.w, v0.w);
        mn.x = fminf(mn.x, v0.x); mn.y = fminf(mn.y, v0.y);
        mn.z = fminf(mn.z, v0.z); mn.w = fminf(mn.w, v0.w);

        s.x += v1.x; s.y += v1.y; s.z += v1.z; s.w += v1.w;
        mx.x = fmaxf(mx.x, v1.x); mx.y = fmaxf(mx.y, v1.y);
        mx.z = fmaxf(mx.z, v1.z); mx.w = fmaxf(mx.w, v1.w);
        mn.x = fminf(mn.x, v1.x); mn.y = fminf(mn.y, v1.y);
        mn.z = fminf(mn.z, v1.z); mn.w = fminf(mn.w, v1.w);

        s.x += v2.x; s.y += v2.y; s.z += v2.z; s.w += v2.w;
        mx.x = fmaxf(mx.x, v2.x); mx.y = fmaxf(mx.y, v2.y);
        mx.z = fmaxf(mx.z, v2.z); mx.w = fmaxf(mx.w, v2.w);
        mn.x = fminf(mn.x, v2.x); mn.y = fminf(mn.y, v2.y);
        mn.z = fminf(mn.z, v2.z); mn.w = fminf(mn.w, v2.w);

        s.x += v3.x; s.y += v3.y; s.z += v3.z; s.w += v3.w;
        mx.x = fmaxf(mx.x, v3.x); mx.y = fmaxf(mx.y, v3.y);
        mx.z = fmaxf(mx.z, v3.z); mx.w = fmaxf(mx.w, v3.w);
        mn.x = fminf(mn.x, v3.x); mn.y = fminf(mn.y, v3.y);
        mn.z = fminf(mn.z, v3.z); mn.w = fminf(mn.w, v3.w);
    }

    __shared__ float4 shS[128], shA[128], shI[128];
    if (tr == 1) { shS[tc] = s; shA[tc] = mx; shI[tc] = mn; }
    __syncthreads();
    if (tr == 0) {
        float4 s2 = shS[tc], a2 = shA[tc], i2 = shI[tc];
        s.x += s2.x; s.y += s2.y; s.z += s2.z; s.w += s2.w;
        mx.x = fmaxf(mx.x, a2.x); mx.y = fmaxf(mx.y, a2.y);
        mx.z = fmaxf(mx.z, a2.z); mx.w = fmaxf(mx.w, a2.w);
        mn.x = fminf(mn.x, i2.x); mn.y = fminf(mn.y, i2.y);
        mn.z = fminf(mn.z, i2.z); mn.w = fminf(mn.w, i2.w);
        __stcs(reinterpret_cast<float4*>(g_sumP[b]) + tc, s);
        __stcs(reinterpret_cast<float4*>(g_maxP[b]) + tc, mx);
        __stcs(reinterpret_cast<float4*>(g_minP[b]) + tc, mn);
    }
}

// ---------------------------------------------------------------------------
// Stage 2a: 64 blocks x 512 threads. Block b reduces whole partial rows
// [b*32, b*32+32): thread j owns column j -> fully coalesced 2 KiB row
// reads. Emits one row per block.
// ---------------------------------------------------------------------------
__global__ void k_stage2a() {
    const int j = threadIdx.x;    // column 0..511
    const int b = blockIdx.x;     // 0..63
    const int r0 = b * (NB1 / NB2);   // 32 rows each

    float s = 0.f, mx = -INFINITY, mn = INFINITY;
#pragma unroll 8
    for (int r = 0; r < NB1 / NB2; r++) {
        s += g_sumP[r0 + r][j];
        mx = fmaxf(mx, g_maxP[r0 + r][j]);
        mn = fminf(mn, g_minP[r0 + r][j]);
    }
    g_sum2[b][j] = s;
    g_max2[b][j] = mx;
    g_min2[b][j] = mn;
}

// ---------------------------------------------------------------------------
// Stage 2b: one block, 512 threads. Finishes the 64-row reduce per column,
// computes mean/u/dev, three global maxima -> SN1/SN2/SN3, and the fused
// per-column constants for pass3.
// ---------------------------------------------------------------------------
__device__ __forceinline__ float pow2_floor_log2(float v) {
    // replicates exp2(floor(log2(floor(v)))) including the v<1 -> 0 edge
    float f = floorf(v);
    if (f < 1.0f) return 0.0f;
    return ldexpf(1.0f, ilogbf(f));
}

__global__ void k_stage2b(const float* __restrict__ w,
                          const float* __restrict__ bia) {
    const int j = threadIdx.x;  // 0..511

    float s = 0.f, mx = -INFINITY, mn = INFINITY;
#pragma unroll
    for (int r = 0; r < NB2; r++) {
        s += g_sum2[r][j];
        mx = fmaxf(mx, g_max2[r][j]);
        mn = fminf(mn, g_min2[r][j]);
    }
    const float cb = (float)(1.0 / sqrt(2.0 * log((double)BDIM)));
    float mean = s * (1.0f / (float)BDIM);     // /2^16: exact scaling
    float uv   = cb * (mx - mn);
    float dev  = fmaxf(mx - mean, mean - mn);  // = max_i |x[i,j]-mean_j|

    float wv = w[j];
    float bv = bia[j];

    __shared__ float sh[CDIM];
    __shared__ float s_dmax, s_wmax, s_sn1, s_sn2, s_sn3;

    // dmax = max over cols of max(|q|_col, |u|_col)
    sh[j] = fmaxf(dev, fabsf(uv));
    __syncthreads();
    for (int off = 256; off > 0; off >>= 1) {
        if (j < off) sh[j] = fmaxf(sh[j], sh[j + off]);
        __syncthreads();
    }
    if (j == 0) s_dmax = (sh[0] == 0.f) ? 1.f : sh[0];
    __syncthreads();

    sh[j] = fabsf(wv);
    __syncthreads();
    for (int off = 256; off > 0; off >>= 1) {
        if (j < off) sh[j] = fmaxf(sh[j], sh[j + off]);
        __syncthreads();
    }
    if (j == 0) s_wmax = (sh[0] == 0.f) ? 1.f : sh[0];
    __syncthreads();

    sh[j] = fabsf(bv);
    __syncthreads();
    for (int off = 256; off > 0; off >>= 1) {
        if (j < off) sh[j] = fmaxf(sh[j], sh[j + off]);
        __syncthreads();
    }
    if (j == 0) {
        float bmax = (sh[0] == 0.f) ? 1.f : sh[0];
        s_sn1 = pow2_floor_log2(32.0f / s_dmax);
        s_sn2 = pow2_floor_log2(32.0f / s_wmax);
        s_sn3 = pow2_floor_log2(32.0f / bmax);
        g_sn1 = s_sn1;
    }
    __syncthreads();

    const float SN1 = s_sn1, SN2 = s_sn2, SN3 = s_sn3;

    int uu = (int)(uv * SN1);       // trunc toward zero == astype(int32)
    int ww = (int)(wv * SN2);
    int bq = (int)(bv * SN3);

    int iu = min(abs(uu), 64);
    int ib = min(abs(bq), 64);
    float sgu = (uv > 0.f) ? 1.f : ((uv < 0.f) ? -1.f : 0.f);
    float sgb = (bv > 0.f) ? 1.f : ((bv < 0.f) ? -1.f : 0.f);
    float x8 = (float)(iu * ib) * sgu * sgb;

    float ssv = (float)uu * SN2 * SN3;
    g_mean[j] = mean;
    g_c1[j]   = SN3 / ssv;          // x7 coefficient
    g_c2[j]   = x8 * SN2 / ssv;     // additive term

    int wc = max(-64, min(64, ww)); // signed-clamp == sign*clip(|.|,64)
    g_wc[j] = (float)wc;
}

// ---------------------------------------------------------------------------
// Pass 3: elementwise output, reversed block order, BATCHED LOADS: each
// iteration issues 2 row-pair loads before any compute/store (per-thread
// load MLP >= 2, mirroring pass1's proven batching win). X loads default
// policy; output stores __stcs. w-group g = row>>7 (repeat_interleave
// pairing: k//B == row>>7 exactly).
// out = clamp((int)((x-mean)*SN1), +-64) * (wc[g]*c1[j]) + c2[j]
// ---------------------------------------------------------------------------
__device__ __forceinline__ float4 sc_map(float4 v, float4 m, float4 e1,
                                         float4 c2, float sn1) {
    float4 o;
    int qx = (int)((v.x - m.x) * sn1); qx = max(-64, min(64, qx));
    int qy = (int)((v.y - m.y) * sn1); qy = max(-64, min(64, qy));
    int qz = (int)((v.z - m.z) * sn1); qz = max(-64, min(64, qz));
    int qw = (int)((v.w - m.w) * sn1); qw = max(-64, min(64, qw));
    o.x = (float)qx * e1.x + c2.x;
    o.y = (float)qy * e1.y + c2.y;
    o.z = (float)qz * e1.z + c2.z;
    o.w = (float)qw * e1.w + c2.w;
    return o;
}

__global__ void __launch_bounds__(256) k_pass3(const float* __restrict__ X,
                                               float* __restrict__ O) {
    const int tc = threadIdx.x & 127;   // column group 0..127
    const int tr = threadIdx.x >> 7;    // row parity 0..1
    const int row0 = BDIM - (blockIdx.x + 1) * R3;   // reversed order
    const int g = row0 >> 7;            // 32-row blocks never straddle groups

    float4 m  = reinterpret_cast<const float4*>(g_mean)[tc];
    float4 c1 = reinterpret_cast<const float4*>(g_c1)[tc];
    float4 c2 = reinterpret_cast<const float4*>(g_c2)[tc];
    const float wg  = g_wc[g];
    const float sn1 = g_sn1;
    float4 e1;
    e1.x = wg * c1.x; e1.y = wg * c1.y; e1.z = wg * c1.z; e1.w = wg * c1.w;

    const float4* Xp = reinterpret_cast<const float4*>(X);
    float4* Op = reinterpret_cast<float4*>(O);
    const size_t rs = CDIM / 4;
    size_t base = (size_t)(row0 + tr) * rs + tc;

#pragma unroll
    for (int r = 0; r < R3; r += 4) {   // 2 row-pairs per iteration
        // issue both loads before any compute
        float4 va = Xp[base + (size_t)(r + 0) * rs];
        float4 vb = Xp[base + (size_t)(r + 2) * rs];
        float4 oa = sc_map(va, m, e1, c2, sn1);
        float4 ob = sc_map(vb, m, e1, c2, sn1);
        __stcs(Op + base + (size_t)(r + 0) * rs, oa);
        __stcs(Op + base + (size_t)(r + 2) * rs, ob);
    }
}

// ---------------------------------------------------------------------------
extern "C" void kernel_launch(void* const* d_in, const int* in_sizes, int n_in,
                              void* d_out, int out_size) {
    const float* X  = (const float*)d_in[0];   // (65536, 512)
    const float* w  = (const float*)d_in[1];   // (512,)
    const float* bi = (const float*)d_in[2];   // (512,)
    float* O = (float*)d_out;

    k_pass1<<<NB1, 256>>>(X);
    k_stage2a<<<NB2, CDIM>>>();
    k_stage2b<<<1, CDIM>>>(w, bi);
    k_pass3<<<NB3, 256>>>(X, O);
}